// round 15
// baseline (speedup 1.0000x reference)
#include <cuda_runtime.h>
#include <cfloat>

#define NCOLS 1000
#define NVEC  250          // float4s per row per array
#define HALF  64           // threads per row
#define TPB   128          // 2 rows per CTA
#define NWARP_HALF 2

// Order-preserving float<->uint mapping
__device__ __forceinline__ unsigned ford(float f) {
    unsigned u = __float_as_uint(f);
    return ((int)u < 0) ? ~u : (u | 0x80000000u);
}
__device__ __forceinline__ float funord(unsigned u) {
    return __uint_as_float(((int)u < 0) ? (u ^ 0x80000000u) : ~u);
}

// Exact warp top-2 in ordered-uint domain (per-lane o1 >= o2 on entry).
__device__ __forceinline__ void warp_top2(unsigned& o1, unsigned& o2) {
    unsigned r1  = __reduce_max_sync(0xFFFFFFFFu, o1);
    unsigned bal = __ballot_sync(0xFFFFFFFFu, o1 == r1);
    unsigned u   = (o1 == r1) ? o2 : o1;
    unsigned r2  = __reduce_max_sync(0xFFFFFFFFu, u);
    if (__popc(bal) > 1) r2 = r1;   // duplicated max across lanes -> t2 == t1
    o1 = r1; o2 = r2;
}

// Branchless exact top-2 of 8 (FMNMX tournament)
__device__ __forceinline__ void top2_8(const float* v, float& t1, float& t2) {
    float m0 = fmaxf(v[0], v[1]), n0 = fminf(v[0], v[1]);
    float m1 = fmaxf(v[2], v[3]), n1 = fminf(v[2], v[3]);
    float m2 = fmaxf(v[4], v[5]), n2 = fminf(v[4], v[5]);
    float m3 = fmaxf(v[6], v[7]), n3 = fminf(v[6], v[7]);
    float a1 = fmaxf(m0, m1), a2 = fmaxf(fminf(m0, m1), fmaxf(n0, n1));
    float b1 = fmaxf(m2, m3), b2 = fmaxf(fminf(m2, m3), fmaxf(n2, n3));
    t1 = fmaxf(a1, b1);
    t2 = fmaxf(fminf(a1, b1), fmaxf(a2, b2));
}

// Exact top-2 of 16 = merge of two top2_8
__device__ __forceinline__ void top2_16(const float* v, float& t1, float& t2) {
    float p1, p2, q1, q2;
    top2_8(v, p1, p2);
    top2_8(v + 8, q1, q2);
    t1 = fmaxf(p1, q1);
    t2 = fmaxf(fminf(p1, q1), fmaxf(p2, q2));
}

// Merge (t1,t2) pair q into accumulator
__device__ __forceinline__ void pair_merge(float& t1, float& t2, float q1, float q2) {
    float mn = fminf(t1, q1);
    t1 = fmaxf(t1, q1);
    t2 = fmaxf(mn, fmaxf(t2, q2));
}

__global__ __launch_bounds__(TPB)
void netsat1_kernel(const float* __restrict__ y1,
                    const float* __restrict__ y2,
                    float* __restrict__ out)
{
    const int t    = threadIdx.x;
    const int half = t >> 6;            // 0 or 1: which row this thread works on
    const int tl   = t & (HALF - 1);    // thread index within the half (0..63)
    const int row  = blockIdx.x * 2 + half;
    const int hwid = tl >> 5;           // warp-within-half (0 or 1)
    const int lid  = t & 31;

    const float4* r1 = reinterpret_cast<const float4*>(y1 + (size_t)row * NCOLS);
    const float4* r2 = reinterpret_cast<const float4*>(y2 + (size_t)row * NCOLS);

    // 4 float4 chunks per array: tl, tl+64, tl+128 always valid (<250); tl+192 valid for tl<58
    float a[16], b[16];
    const bool c3 = (tl < NVEC - 3 * HALF);   // tl < 58
    {
        float4 v0 = __ldcs(&r1[tl]);
        float4 v1 = __ldcs(&r1[tl + HALF]);
        float4 v2 = __ldcs(&r1[tl + 2 * HALF]);
        float4 w0 = __ldcs(&r2[tl]);
        float4 w1 = __ldcs(&r2[tl + HALF]);
        float4 w2 = __ldcs(&r2[tl + 2 * HALF]);
        float4 v3, w3;
        if (c3) { v3 = __ldcs(&r1[tl + 3 * HALF]); w3 = __ldcs(&r2[tl + 3 * HALF]); }
        else    { v3 = make_float4(-FLT_MAX,-FLT_MAX,-FLT_MAX,-FLT_MAX); w3 = v3; }
        a[0]=v0.x; a[1]=v0.y; a[2]=v0.z; a[3]=v0.w;
        a[4]=v1.x; a[5]=v1.y; a[6]=v1.z; a[7]=v1.w;
        a[8]=v2.x; a[9]=v2.y; a[10]=v2.z; a[11]=v2.w;
        a[12]=v3.x; a[13]=v3.y; a[14]=v3.z; a[15]=v3.w;
        b[0]=w0.x; b[1]=w0.y; b[2]=w0.z; b[3]=w0.w;
        b[4]=w1.x; b[5]=w1.y; b[6]=w1.z; b[7]=w1.w;
        b[8]=w2.x; b[9]=w2.y; b[10]=w2.z; b[11]=w2.w;
        b[12]=w3.x; b[13]=w3.y; b[14]=w3.z; b[15]=w3.w;
    }

    // --- Pass 1: per-thread exact top-2 of 16, then warp top-2 (within half) ---
    float ta1, ta2, tb1, tb2;
    top2_16(a, ta1, ta2);
    top2_16(b, tb1, tb2);

    unsigned oa1 = ford(ta1), oa2 = ford(ta2);
    unsigned ob1 = ford(tb1), ob2 = ford(tb2);
    warp_top2(oa1, oa2);
    warp_top2(ob1, ob2);

    __shared__ float4 sw[2][NWARP_HALF];
    __shared__ unsigned smax[2][NWARP_HALF];

    if (lid == 0)
        sw[half][hwid] = make_float4(funord(oa1), funord(oa2), funord(ob1), funord(ob2));
    __syncthreads();   // all 128 threads participate

    // Merge this half's 2 warp pairs (redundant across the half's threads)
    float4 s0 = sw[half][0], s1 = sw[half][1];
    float t1_1 = s0.x, t2_1 = s0.y, t1_2 = s0.z, t2_2 = s0.w;
    pair_merge(t1_1, t2_1, s1.x, s1.y);
    pair_merge(t1_2, t2_2, s1.z, s1.w);

    // --- Pass 2 (registers), shifted domain:
    // min(y1-t1_1, y2-t1_2) = min(y1, y2 + d) - t1_1,  d = t1_1 - t1_2
    const float d = t1_1 - t1_2;
    float m = -FLT_MAX;
    #pragma unroll
    for (int k = 0; k < 16; ++k)
        m = fmaxf(m, fminf(a[k], b[k] + d));

    // Fixup iff this thread holds a row-argmax element of either array (cold).
    if ((ta1 == t1_1) || (tb1 == t1_2)) {
        #pragma unroll
        for (int k = 0; k < 16; ++k) {
            if (a[k] == t1_1 || b[k] == t1_2) {
                float loo1 = (a[k] == t1_1) ? t2_1 : t1_1;
                float loo2 = (b[k] == t1_2) ? t2_2 : t1_2;
                m = fmaxf(m, fminf(a[k] - loo1, b[k] - loo2) + t1_1);  // shifted
            }
        }
    }

    // --- Half max reduce (2 warps per half) ---
    unsigned om = __reduce_max_sync(0xFFFFFFFFu, ford(m));
    if (lid == 0) smax[half][hwid] = om;
    __syncthreads();   // all 128 threads participate
    if (tl == 0)
        __stcs(&out[row], funord(max(smax[half][0], smax[half][1])) - t1_1);   // un-shift
}

extern "C" void kernel_launch(void* const* d_in, const int* in_sizes, int n_in,
                              void* d_out, int out_size)
{
    const float* y1 = (const float*)d_in[0];
    const float* y2 = (const float*)d_in[1];
    float* out = (float*)d_out;

    const int B = in_sizes[0] / NCOLS;   // 16384
    netsat1_kernel<<<B / 2, TPB>>>(y1, y2, out);
}

// round 16
// speedup vs baseline: 1.1726x; 1.1726x over previous
#include <cuda_runtime.h>
#include <cfloat>

#define NCOLS 1000
#define NVEC  250          // float4s per row per array
#define TPB   64
#define NWARP (TPB / 32)   // 2

// Order-preserving float<->uint mapping
__device__ __forceinline__ unsigned ford(float f) {
    unsigned u = __float_as_uint(f);
    return ((int)u < 0) ? ~u : (u | 0x80000000u);
}
__device__ __forceinline__ float funord(unsigned u) {
    return __uint_as_float(((int)u < 0) ? (u ^ 0x80000000u) : ~u);
}

// Exact warp top-2 in ordered-uint domain (per-lane o1 >= o2 on entry).
__device__ __forceinline__ void warp_top2(unsigned& o1, unsigned& o2) {
    unsigned r1  = __reduce_max_sync(0xFFFFFFFFu, o1);
    unsigned bal = __ballot_sync(0xFFFFFFFFu, o1 == r1);
    unsigned u   = (o1 == r1) ? o2 : o1;
    unsigned r2  = __reduce_max_sync(0xFFFFFFFFu, u);
    if (__popc(bal) > 1) r2 = r1;   // duplicated max across lanes -> t2 == t1
    o1 = r1; o2 = r2;
}

// Branchless exact top-2 of 8 (FMNMX tournament)
__device__ __forceinline__ void top2_8(const float* v, float& t1, float& t2) {
    float m0 = fmaxf(v[0], v[1]), n0 = fminf(v[0], v[1]);
    float m1 = fmaxf(v[2], v[3]), n1 = fminf(v[2], v[3]);
    float m2 = fmaxf(v[4], v[5]), n2 = fminf(v[4], v[5]);
    float m3 = fmaxf(v[6], v[7]), n3 = fminf(v[6], v[7]);
    float a1 = fmaxf(m0, m1), a2 = fmaxf(fminf(m0, m1), fmaxf(n0, n1));
    float b1 = fmaxf(m2, m3), b2 = fmaxf(fminf(m2, m3), fmaxf(n2, n3));
    t1 = fmaxf(a1, b1);
    t2 = fmaxf(fminf(a1, b1), fmaxf(a2, b2));
}

// Exact top-2 of 16 = merge of two top2_8
__device__ __forceinline__ void top2_16(const float* v, float& t1, float& t2) {
    float p1, p2, q1, q2;
    top2_8(v, p1, p2);
    top2_8(v + 8, q1, q2);
    t1 = fmaxf(p1, q1);
    t2 = fmaxf(fminf(p1, q1), fmaxf(p2, q2));
}

// Merge (t1,t2) pair q into accumulator
__device__ __forceinline__ void pair_merge(float& t1, float& t2, float q1, float q2) {
    float mn = fminf(t1, q1);
    t1 = fmaxf(t1, q1);
    t2 = fmaxf(mn, fmaxf(t2, q2));
}

__global__ __launch_bounds__(TPB, 12)
void netsat1_kernel(const float* __restrict__ y1,
                    const float* __restrict__ y2,
                    float* __restrict__ out)
{
    const int row = blockIdx.x;
    const int t   = threadIdx.x;
    const int wid = t >> 5;
    const int lid = t & 31;

    const float4* r1 = reinterpret_cast<const float4*>(y1 + (size_t)row * NCOLS);
    const float4* r2 = reinterpret_cast<const float4*>(y2 + (size_t)row * NCOLS);

    // 4 float4 chunks per array: t, t+64, t+128 always valid (<250); t+192 valid for t<58
    float a[16], b[16];
    const bool c3 = (t < NVEC - 3 * TPB);   // t < 58
    {
        float4 v0 = __ldcs(&r1[t]);
        float4 v1 = __ldcs(&r1[t + TPB]);
        float4 v2 = __ldcs(&r1[t + 2 * TPB]);
        float4 w0 = __ldcs(&r2[t]);
        float4 w1 = __ldcs(&r2[t + TPB]);
        float4 w2 = __ldcs(&r2[t + 2 * TPB]);
        float4 v3, w3;
        if (c3) { v3 = __ldcs(&r1[t + 3 * TPB]); w3 = __ldcs(&r2[t + 3 * TPB]); }
        else    { v3 = make_float4(-FLT_MAX,-FLT_MAX,-FLT_MAX,-FLT_MAX); w3 = v3; }
        a[0]=v0.x; a[1]=v0.y; a[2]=v0.z; a[3]=v0.w;
        a[4]=v1.x; a[5]=v1.y; a[6]=v1.z; a[7]=v1.w;
        a[8]=v2.x; a[9]=v2.y; a[10]=v2.z; a[11]=v2.w;
        a[12]=v3.x; a[13]=v3.y; a[14]=v3.z; a[15]=v3.w;
        b[0]=w0.x; b[1]=w0.y; b[2]=w0.z; b[3]=w0.w;
        b[4]=w1.x; b[5]=w1.y; b[6]=w1.z; b[7]=w1.w;
        b[8]=w2.x; b[9]=w2.y; b[10]=w2.z; b[11]=w2.w;
        b[12]=w3.x; b[13]=w3.y; b[14]=w3.z; b[15]=w3.w;
    }

    // --- Pass 1: per-thread exact top-2 of 16, then warp top-2 ---
    float ta1, ta2, tb1, tb2;
    top2_16(a, ta1, ta2);
    top2_16(b, tb1, tb2);

    unsigned oa1 = ford(ta1), oa2 = ford(ta2);
    unsigned ob1 = ford(tb1), ob2 = ford(tb2);
    warp_top2(oa1, oa2);
    warp_top2(ob1, ob2);

    __shared__ float4 sw[NWARP];
    __shared__ unsigned smax[NWARP];

    if (lid == 0)
        sw[wid] = make_float4(funord(oa1), funord(oa2), funord(ob1), funord(ob2));
    __syncthreads();

    // Merge the 2 warp pairs (redundant in all threads; 8 FMNMX)
    float4 s0 = sw[0], s1 = sw[1];
    float t1_1 = s0.x, t2_1 = s0.y, t1_2 = s0.z, t2_2 = s0.w;
    pair_merge(t1_1, t2_1, s1.x, s1.y);
    pair_merge(t1_2, t2_2, s1.z, s1.w);

    // --- Pass 2 (registers), shifted domain:
    // min(y1-t1_1, y2-t1_2) = min(y1, y2 + d) - t1_1,  d = t1_1 - t1_2
    const float d = t1_1 - t1_2;
    float m = -FLT_MAX;
    #pragma unroll
    for (int k = 0; k < 16; ++k)
        m = fmaxf(m, fminf(a[k], b[k] + d));

    // Fixup iff this thread holds a row-argmax element of either array (cold).
    if ((ta1 == t1_1) || (tb1 == t1_2)) {
        #pragma unroll
        for (int k = 0; k < 16; ++k) {
            if (a[k] == t1_1 || b[k] == t1_2) {
                float loo1 = (a[k] == t1_1) ? t2_1 : t1_1;
                float loo2 = (b[k] == t1_2) ? t2_2 : t1_2;
                m = fmaxf(m, fminf(a[k] - loo1, b[k] - loo2) + t1_1);  // shifted
            }
        }
    }

    // --- Block max reduce of m (2 warps) ---
    unsigned om = __reduce_max_sync(0xFFFFFFFFu, ford(m));
    if (lid == 0) smax[wid] = om;
    __syncthreads();
    if (t == 0)
        __stcs(&out[row], funord(max(smax[0], smax[1])) - t1_1);   // un-shift
}

extern "C" void kernel_launch(void* const* d_in, const int* in_sizes, int n_in,
                              void* d_out, int out_size)
{
    const float* y1 = (const float*)d_in[0];
    const float* y2 = (const float*)d_in[1];
    float* out = (float*)d_out;

    const int B = in_sizes[0] / NCOLS;   // 16384
    netsat1_kernel<<<B, TPB>>>(y1, y2, out);
}

// round 17
// speedup vs baseline: 1.2798x; 1.0914x over previous
#include <cuda_runtime.h>
#include <cfloat>

#define NCOLS 1000
#define NVEC  250          // float4s per row per array
#define TPB   64
#define NWARP (TPB / 32)   // 2

// Streaming 128-bit load with 256B L2 prefetch-size hint
__device__ __forceinline__ float4 ldcs_256(const float4* p) {
    float4 v;
    asm volatile("ld.global.cs.L2::256B.v4.f32 {%0,%1,%2,%3}, [%4];"
                 : "=f"(v.x), "=f"(v.y), "=f"(v.z), "=f"(v.w)
                 : "l"(p));
    return v;
}

// Order-preserving float<->uint mapping
__device__ __forceinline__ unsigned ford(float f) {
    unsigned u = __float_as_uint(f);
    return ((int)u < 0) ? ~u : (u | 0x80000000u);
}
__device__ __forceinline__ float funord(unsigned u) {
    return __uint_as_float(((int)u < 0) ? (u ^ 0x80000000u) : ~u);
}

// Exact warp top-2 in ordered-uint domain (per-lane o1 >= o2 on entry).
__device__ __forceinline__ void warp_top2(unsigned& o1, unsigned& o2) {
    unsigned r1  = __reduce_max_sync(0xFFFFFFFFu, o1);
    unsigned bal = __ballot_sync(0xFFFFFFFFu, o1 == r1);
    unsigned u   = (o1 == r1) ? o2 : o1;
    unsigned r2  = __reduce_max_sync(0xFFFFFFFFu, u);
    if (__popc(bal) > 1) r2 = r1;   // duplicated max across lanes -> t2 == t1
    o1 = r1; o2 = r2;
}

// Branchless exact top-2 of 8 (FMNMX tournament)
__device__ __forceinline__ void top2_8(const float* v, float& t1, float& t2) {
    float m0 = fmaxf(v[0], v[1]), n0 = fminf(v[0], v[1]);
    float m1 = fmaxf(v[2], v[3]), n1 = fminf(v[2], v[3]);
    float m2 = fmaxf(v[4], v[5]), n2 = fminf(v[4], v[5]);
    float m3 = fmaxf(v[6], v[7]), n3 = fminf(v[6], v[7]);
    float a1 = fmaxf(m0, m1), a2 = fmaxf(fminf(m0, m1), fmaxf(n0, n1));
    float b1 = fmaxf(m2, m3), b2 = fmaxf(fminf(m2, m3), fmaxf(n2, n3));
    t1 = fmaxf(a1, b1);
    t2 = fmaxf(fminf(a1, b1), fmaxf(a2, b2));
}

// Exact top-2 of 16 = merge of two top2_8
__device__ __forceinline__ void top2_16(const float* v, float& t1, float& t2) {
    float p1, p2, q1, q2;
    top2_8(v, p1, p2);
    top2_8(v + 8, q1, q2);
    t1 = fmaxf(p1, q1);
    t2 = fmaxf(fminf(p1, q1), fmaxf(p2, q2));
}

// Merge (t1,t2) pair q into accumulator
__device__ __forceinline__ void pair_merge(float& t1, float& t2, float q1, float q2) {
    float mn = fminf(t1, q1);
    t1 = fmaxf(t1, q1);
    t2 = fmaxf(mn, fmaxf(t2, q2));
}

__global__ __launch_bounds__(TPB, 12)
void netsat1_kernel(const float* __restrict__ y1,
                    const float* __restrict__ y2,
                    float* __restrict__ out)
{
    const int row = blockIdx.x;
    const int t   = threadIdx.x;
    const int wid = t >> 5;
    const int lid = t & 31;

    const float4* r1 = reinterpret_cast<const float4*>(y1 + (size_t)row * NCOLS);
    const float4* r2 = reinterpret_cast<const float4*>(y2 + (size_t)row * NCOLS);

    // 4 float4 chunks per array: t, t+64, t+128 always valid (<250); t+192 valid for t<58
    float a[16], b[16];
    const bool c3 = (t < NVEC - 3 * TPB);   // t < 58
    {
        float4 v0 = ldcs_256(&r1[t]);
        float4 v1 = ldcs_256(&r1[t + TPB]);
        float4 v2 = ldcs_256(&r1[t + 2 * TPB]);
        float4 w0 = ldcs_256(&r2[t]);
        float4 w1 = ldcs_256(&r2[t + TPB]);
        float4 w2 = ldcs_256(&r2[t + 2 * TPB]);
        float4 v3, w3;
        if (c3) { v3 = ldcs_256(&r1[t + 3 * TPB]); w3 = ldcs_256(&r2[t + 3 * TPB]); }
        else    { v3 = make_float4(-FLT_MAX,-FLT_MAX,-FLT_MAX,-FLT_MAX); w3 = v3; }
        a[0]=v0.x; a[1]=v0.y; a[2]=v0.z; a[3]=v0.w;
        a[4]=v1.x; a[5]=v1.y; a[6]=v1.z; a[7]=v1.w;
        a[8]=v2.x; a[9]=v2.y; a[10]=v2.z; a[11]=v2.w;
        a[12]=v3.x; a[13]=v3.y; a[14]=v3.z; a[15]=v3.w;
        b[0]=w0.x; b[1]=w0.y; b[2]=w0.z; b[3]=w0.w;
        b[4]=w1.x; b[5]=w1.y; b[6]=w1.z; b[7]=w1.w;
        b[8]=w2.x; b[9]=w2.y; b[10]=w2.z; b[11]=w2.w;
        b[12]=w3.x; b[13]=w3.y; b[14]=w3.z; b[15]=w3.w;
    }

    // --- Pass 1: per-thread exact top-2 of 16, then warp top-2 ---
    float ta1, ta2, tb1, tb2;
    top2_16(a, ta1, ta2);
    top2_16(b, tb1, tb2);

    unsigned oa1 = ford(ta1), oa2 = ford(ta2);
    unsigned ob1 = ford(tb1), ob2 = ford(tb2);
    warp_top2(oa1, oa2);
    warp_top2(ob1, ob2);

    __shared__ float4 sw[NWARP];
    __shared__ unsigned smax[NWARP];

    if (lid == 0)
        sw[wid] = make_float4(funord(oa1), funord(oa2), funord(ob1), funord(ob2));
    __syncthreads();

    // Merge the 2 warp pairs (redundant in all threads; 8 FMNMX)
    float4 s0 = sw[0], s1 = sw[1];
    float t1_1 = s0.x, t2_1 = s0.y, t1_2 = s0.z, t2_2 = s0.w;
    pair_merge(t1_1, t2_1, s1.x, s1.y);
    pair_merge(t1_2, t2_2, s1.z, s1.w);

    // --- Pass 2 (registers), shifted domain:
    // min(y1-t1_1, y2-t1_2) = min(y1, y2 + d) - t1_1,  d = t1_1 - t1_2
    const float d = t1_1 - t1_2;
    float m = -FLT_MAX;
    #pragma unroll
    for (int k = 0; k < 16; ++k)
        m = fmaxf(m, fminf(a[k], b[k] + d));

    // Fixup iff this thread holds a row-argmax element of either array (cold).
    if ((ta1 == t1_1) || (tb1 == t1_2)) {
        #pragma unroll
        for (int k = 0; k < 16; ++k) {
            if (a[k] == t1_1 || b[k] == t1_2) {
                float loo1 = (a[k] == t1_1) ? t2_1 : t1_1;
                float loo2 = (b[k] == t1_2) ? t2_2 : t1_2;
                m = fmaxf(m, fminf(a[k] - loo1, b[k] - loo2) + t1_1);  // shifted
            }
        }
    }

    // --- Block max reduce of m (2 warps) ---
    unsigned om = __reduce_max_sync(0xFFFFFFFFu, ford(m));
    if (lid == 0) smax[wid] = om;
    __syncthreads();
    if (t == 0)
        __stcs(&out[row], funord(max(smax[0], smax[1])) - t1_1);   // un-shift
}

extern "C" void kernel_launch(void* const* d_in, const int* in_sizes, int n_in,
                              void* d_out, int out_size)
{
    const float* y1 = (const float*)d_in[0];
    const float* y2 = (const float*)d_in[1];
    float* out = (float*)d_out;

    const int B = in_sizes[0] / NCOLS;   // 16384
    netsat1_kernel<<<B, TPB>>>(y1, y2, out);
}